// round 1
// baseline (speedup 1.0000x reference)
#include <cuda_runtime.h>
#include <cstdint>

#define MAXN 50000
#define MAXE 800000
#define HID 128

// ---- static scratch (no allocations allowed) ----
__device__ float g_buf0[(size_t)MAXN * HID];
__device__ float g_buf1[(size_t)MAXN * HID];
__device__ float g_buf2[(size_t)MAXN * HID];
__device__ float g_deg[MAXN];
__device__ float g_dinv[MAXN];
__device__ float g_sum[HID];
__device__ float g_sumsq[HID];
__device__ float g_scale[HID];
__device__ float g_shift[HID];

// ---------------------------------------------------------------------------
__global__ void zero_aux(float* __restrict__ deg, float* __restrict__ sum,
                         float* __restrict__ sumsq, int n)
{
    int i = blockIdx.x * blockDim.x + threadIdx.x;
    if (i < n) deg[i] = 0.0f;
    if (i < HID) { sum[i] = 0.0f; sumsq[i] = 0.0f; }
}

__global__ void count_deg(const int* __restrict__ dst, float* __restrict__ deg, int E)
{
    int i = blockIdx.x * blockDim.x + threadIdx.x;
    if (i < E) atomicAdd(&deg[dst[i]], 1.0f);
}

__global__ void compute_dinv(const float* __restrict__ deg, float* __restrict__ dinv, int n)
{
    int i = blockIdx.x * blockDim.x + threadIdx.x;
    if (i < n) dinv[i] = rsqrtf(deg[i] + 1.0f);
}

// ---------------------------------------------------------------------------
// C[M,128] = A[M,128] @ W[128,128], fp32, row-major everywhere.
// BM=128 (block), BN=128 (full width), BK=8, TM=TN=8, 256 threads.
__global__ __launch_bounds__(256)
void sgemm128(const float* __restrict__ A, const float* __restrict__ W,
              float* __restrict__ C, int M)
{
    __shared__ __align__(16) float As[8][128];
    __shared__ __align__(16) float Bs[8][128];

    const int blockRow = blockIdx.x * 128;
    const int tid = threadIdx.x;
    const int tm = tid >> 4;         // 0..15  -> rows tm*8..tm*8+7
    const int tn = tid & 15;         // 0..15  -> cols tn*8..tn*8+7

    const int arow  = tid >> 1;         // 0..127
    const int acol4 = (tid & 1) * 4;    // 0 or 4
    const int brow  = tid >> 5;         // 0..7
    const int bcol4 = (tid & 31) * 4;   // 0..124

    float acc[8][8];
#pragma unroll
    for (int i = 0; i < 8; i++)
#pragma unroll
        for (int j = 0; j < 8; j++) acc[i][j] = 0.0f;

    const int gr_a = blockRow + arow;
    const bool a_ok = (gr_a < M);
    const float4* Ap = (const float4*)(A + (size_t)gr_a * HID + acol4);

    for (int k0 = 0; k0 < 128; k0 += 8) {
        float4 av = a_ok ? Ap[k0 >> 2] : make_float4(0.f, 0.f, 0.f, 0.f);
        As[acol4 + 0][arow] = av.x;
        As[acol4 + 1][arow] = av.y;
        As[acol4 + 2][arow] = av.z;
        As[acol4 + 3][arow] = av.w;
        float4 bv = *(const float4*)(W + (size_t)(k0 + brow) * HID + bcol4);
        *(float4*)(&Bs[brow][bcol4]) = bv;
        __syncthreads();

#pragma unroll
        for (int kk = 0; kk < 8; kk++) {
            float ra[8], rb[8];
#pragma unroll
            for (int i = 0; i < 8; i++) ra[i] = As[kk][tm * 8 + i];
#pragma unroll
            for (int j = 0; j < 8; j++) rb[j] = Bs[kk][tn * 8 + j];
#pragma unroll
            for (int i = 0; i < 8; i++)
#pragma unroll
                for (int j = 0; j < 8; j++) acc[i][j] += ra[i] * rb[j];
        }
        __syncthreads();
    }

#pragma unroll
    for (int i = 0; i < 8; i++) {
        int gr = blockRow + tm * 8 + i;
        if (gr < M) {
            float4 v0 = make_float4(acc[i][0], acc[i][1], acc[i][2], acc[i][3]);
            float4 v1 = make_float4(acc[i][4], acc[i][5], acc[i][6], acc[i][7]);
            *(float4*)(C + (size_t)gr * HID + tn * 8)     = v0;
            *(float4*)(C + (size_t)gr * HID + tn * 8 + 4) = v1;
        }
    }
}

// ---------------------------------------------------------------------------
// agg[n,:] = h[n,:] * dinv[n]^2 + b[:]
__global__ void self_loop_init(const float* __restrict__ h, const float* __restrict__ dinv,
                               const float* __restrict__ b, float* __restrict__ agg, int Nn)
{
    int idx = blockIdx.x * blockDim.x + threadIdx.x;   // one float4 per thread
    int total = Nn * (HID / 4);
    if (idx >= total) return;
    int n  = idx >> 5;
    int c4 = (idx & 31) * 4;
    float di = dinv[n];
    float w  = di * di;
    float4 v  = *(const float4*)(h + (size_t)n * HID + c4);
    float4 bb = *(const float4*)(b + c4);
    v.x = v.x * w + bb.x;
    v.y = v.y * w + bb.y;
    v.z = v.z * w + bb.z;
    v.w = v.w * w + bb.w;
    *(float4*)(agg + (size_t)n * HID + c4) = v;
}

// agg[dst[e],:] += h[src[e],:] * dinv[src]*dinv[dst]   (one warp per edge)
__global__ void scatter_add(const float* __restrict__ h, float* __restrict__ agg,
                            const int* __restrict__ src, const int* __restrict__ dst,
                            const float* __restrict__ dinv, int E)
{
    int lane = threadIdx.x & 31;
    int warp = (blockIdx.x * blockDim.x + threadIdx.x) >> 5;
    int nwarps = (gridDim.x * blockDim.x) >> 5;
    for (int e = warp; e < E; e += nwarps) {
        int s = src[e], d = dst[e];
        float nrm = dinv[s] * dinv[d];
        float4 v = *(const float4*)(h + (size_t)s * HID + lane * 4);
        v.x *= nrm; v.y *= nrm; v.z *= nrm; v.w *= nrm;
        float* p = agg + (size_t)d * HID + lane * 4;
#if __CUDA_ARCH__ >= 900
        asm volatile("red.global.add.v4.f32 [%0], {%1,%2,%3,%4};"
                     :: "l"(p), "f"(v.x), "f"(v.y), "f"(v.z), "f"(v.w) : "memory");
#else
        atomicAdd(p + 0, v.x);
        atomicAdd(p + 1, v.y);
        atomicAdd(p + 2, v.z);
        atomicAdd(p + 3, v.w);
#endif
    }
}

// ---------------------------------------------------------------------------
__global__ __launch_bounds__(256)
void bn_stats(const float* __restrict__ z, float* __restrict__ sum,
              float* __restrict__ sumsq, int Nn)
{
    int c    = threadIdx.x & 127;
    int half = threadIdx.x >> 7;     // 0 / 1
    float s = 0.f, q = 0.f;
    for (int r = blockIdx.x * 2 + half; r < Nn; r += gridDim.x * 2) {
        float v = z[(size_t)r * HID + c];
        s += v;
        q += v * v;
    }
    __shared__ float sh[256];
    sh[threadIdx.x] = s;
    __syncthreads();
    if (half == 0) atomicAdd(&sum[c], sh[c] + sh[c + 128]);
    __syncthreads();
    sh[threadIdx.x] = q;
    __syncthreads();
    if (half == 0) atomicAdd(&sumsq[c], sh[c] + sh[c + 128]);
}

__global__ void bn_final(const float* __restrict__ sum, const float* __restrict__ sumsq,
                         const float* __restrict__ gamma, const float* __restrict__ beta,
                         float* __restrict__ scale, float* __restrict__ shift, int Nn)
{
    int i = threadIdx.x;
    if (i < HID) {
        float invN = 1.0f / (float)Nn;
        float mean = sum[i] * invN;
        float var  = sumsq[i] * invN - mean * mean;
        float sc   = gamma[i] * rsqrtf(var + 1e-5f);
        scale[i] = sc;
        shift[i] = beta[i] - mean * sc;
    }
}

// z = relu(z*scale + shift), in place
__global__ void bn_apply(float* __restrict__ z, const float* __restrict__ scale,
                         const float* __restrict__ shift, int Nn)
{
    int idx = blockIdx.x * blockDim.x + threadIdx.x;
    int total = Nn * (HID / 4);
    if (idx >= total) return;
    int c4 = (idx & 31) * 4;
    float4 v  = *(float4*)(z + (size_t)idx * 4);
    float4 sc = *(const float4*)(scale + c4);
    float4 sh = *(const float4*)(shift + c4);
    v.x = fmaxf(v.x * sc.x + sh.x, 0.f);
    v.y = fmaxf(v.y * sc.y + sh.y, 0.f);
    v.z = fmaxf(v.z * sc.z + sh.z, 0.f);
    v.w = fmaxf(v.w * sc.w + sh.w, 0.f);
    *(float4*)(z + (size_t)idx * 4) = v;
}

// ---------------------------------------------------------------------------
// out[e] = relu(A[src] + B[dst] + edge_attr[e]@We + bm1) . Wm2 + bm2
// one warp per edge, lane handles 4 contiguous channels
__global__ __launch_bounds__(256)
void edge_mlp(const float* __restrict__ A, const float* __restrict__ B,
              const int* __restrict__ src, const int* __restrict__ dst,
              const float* __restrict__ ea, const float* __restrict__ We,  // [16,128]
              const float* __restrict__ bm1, const float* __restrict__ Wm2,
              const float* __restrict__ bm2, float* __restrict__ out, int E)
{
    __shared__ __align__(16) float sWe[16][128];
    __shared__ __align__(16) float sb[128];
    __shared__ __align__(16) float sw2[128];
    for (int i = threadIdx.x; i < 16 * 128; i += blockDim.x)
        sWe[i >> 7][i & 127] = We[i];
    for (int i = threadIdx.x; i < 128; i += blockDim.x) {
        sb[i]  = bm1[i];
        sw2[i] = Wm2[i];
    }
    __syncthreads();
    const float bm2v = bm2[0];

    int lane = threadIdx.x & 31;
    int warp = (blockIdx.x * blockDim.x + threadIdx.x) >> 5;
    int nw   = (gridDim.x * blockDim.x) >> 5;
    int c4   = lane * 4;

    float4 bias = *(const float4*)(&sb[c4]);
    float4 w2   = *(const float4*)(&sw2[c4]);

    for (int e = warp; e < E; e += nw) {
        int s = src[e], d = dst[e];
        float4 a = *(const float4*)(A + (size_t)s * HID + c4);
        float4 b = *(const float4*)(B + (size_t)d * HID + c4);
        float4 acc;
        acc.x = a.x + b.x + bias.x;
        acc.y = a.y + b.y + bias.y;
        acc.z = a.z + b.z + bias.z;
        acc.w = a.w + b.w + bias.w;

        float eav = (lane < 16) ? ea[(size_t)e * 16 + lane] : 0.0f;
#pragma unroll
        for (int k = 0; k < 16; k++) {
            float ek = __shfl_sync(0xffffffff, eav, k);
            float4 w = *(const float4*)(&sWe[k][c4]);
            acc.x += ek * w.x;
            acc.y += ek * w.y;
            acc.z += ek * w.z;
            acc.w += ek * w.w;
        }
        acc.x = fmaxf(acc.x, 0.f);
        acc.y = fmaxf(acc.y, 0.f);
        acc.z = fmaxf(acc.z, 0.f);
        acc.w = fmaxf(acc.w, 0.f);

        float p = acc.x * w2.x + acc.y * w2.y + acc.z * w2.z + acc.w * w2.w;
#pragma unroll
        for (int o = 16; o; o >>= 1) p += __shfl_xor_sync(0xffffffff, p, o);
        if (lane == 0) out[e] = p + bm2v;
    }
}

// ---------------------------------------------------------------------------
extern "C" void kernel_launch(void* const* d_in, const int* in_sizes, int n_in,
                              void* d_out, int out_size)
{
    const float* x     = (const float*)d_in[0];
    const int*   ei    = (const int*)  d_in[1];
    const float* ea    = (const float*)d_in[2];
    const float* W1    = (const float*)d_in[3];
    const float* b1    = (const float*)d_in[4];
    const float* gamma = (const float*)d_in[5];
    const float* beta  = (const float*)d_in[6];
    const float* W2    = (const float*)d_in[7];
    const float* b2    = (const float*)d_in[8];
    const float* Wm1   = (const float*)d_in[9];
    const float* bm1   = (const float*)d_in[10];
    const float* Wm2   = (const float*)d_in[11];
    const float* bm2   = (const float*)d_in[12];
    float* out = (float*)d_out;

    const int Nn = in_sizes[0] / HID;
    const int E  = in_sizes[1] / 2;
    const int* src = ei;
    const int* dst = ei + E;

    float *buf0, *buf1, *buf2, *deg, *dinv, *sum, *sumsq, *scale, *shift;
    cudaGetSymbolAddress((void**)&buf0,  g_buf0);
    cudaGetSymbolAddress((void**)&buf1,  g_buf1);
    cudaGetSymbolAddress((void**)&buf2,  g_buf2);
    cudaGetSymbolAddress((void**)&deg,   g_deg);
    cudaGetSymbolAddress((void**)&dinv,  g_dinv);
    cudaGetSymbolAddress((void**)&sum,   g_sum);
    cudaGetSymbolAddress((void**)&sumsq, g_sumsq);
    cudaGetSymbolAddress((void**)&scale, g_scale);
    cudaGetSymbolAddress((void**)&shift, g_shift);

    const int gN    = (Nn + 255) / 256;
    const int gE    = (E + 255) / 256;
    const int gElem = (Nn * (HID / 4) + 255) / 256;
    const int gGemm = (Nn + 127) / 128;

    // degree / normalization
    zero_aux<<<gN, 256>>>(deg, sum, sumsq, Nn);
    count_deg<<<gE, 256>>>(dst, deg, E);
    compute_dinv<<<gN, 256>>>(deg, dinv, Nn);

    // conv1: h1 = x @ W1 (buf0); agg1 = scatter + self-loop + b1 (buf1)
    sgemm128<<<gGemm, 256>>>(x, W1, buf0, Nn);
    self_loop_init<<<gElem, 256>>>(buf0, dinv, b1, buf1, Nn);
    scatter_add<<<4096, 256>>>(buf0, buf1, src, dst, dinv, E);

    // batchnorm + relu (in place on buf1)
    bn_stats<<<512, 256>>>(buf1, sum, sumsq, Nn);
    bn_final<<<1, 128>>>(sum, sumsq, gamma, beta, scale, shift, Nn);
    bn_apply<<<gElem, 256>>>(buf1, scale, shift, Nn);

    // conv2: h2 = z @ W2 (buf2); z2 = agg2 (buf0)
    sgemm128<<<gGemm, 256>>>(buf1, W2, buf2, Nn);
    self_loop_init<<<gElem, 256>>>(buf2, dinv, b2, buf0, Nn);
    scatter_add<<<4096, 256>>>(buf2, buf0, src, dst, dinv, E);

    // per-node projections of edge-MLP: A = z2 @ Wm1[0:128], B = z2 @ Wm1[128:256]
    sgemm128<<<gGemm, 256>>>(buf0, Wm1,             buf1, Nn);
    sgemm128<<<gGemm, 256>>>(buf0, Wm1 + 128 * HID, buf2, Nn);

    // fused edge head
    edge_mlp<<<2048, 256>>>(buf1, buf2, src, dst, ea, Wm1 + 256 * HID,
                            bm1, Wm2, bm2, out, E);
}